// round 11
// baseline (speedup 1.0000x reference)
#include <cuda_runtime.h>
#include <cuda_bf16.h>
#include <cstdint>
#include <math.h>

#define NN 100000
#define EE 3200000
#define HDIM 256
#define BN_EPS 1e-5f

// ---------------- device scratch ----------------
__device__ __nv_bfloat16 g_zhi[(size_t)NN * HDIM];
__device__ __nv_bfloat16 g_zlo[(size_t)NN * HDIM];
__device__ __nv_bfloat16 g_thi[(size_t)NN * HDIM];
__device__ __nv_bfloat16 g_tlo[(size_t)NN * HDIM];
__device__ float         g_hA [(size_t)NN * HDIM];
__device__ float         g_hB [(size_t)NN * HDIM];
__device__ __nv_bfloat16 g_w  [6][2][HDIM * HDIM];   // W [K][256] bf16 hi/lo (k-major)
__device__ int g_counts[NN];
__device__ int g_rowptr[NN + 1];
__device__ int g_esrc[EE];
__device__ int g_bsums[128];

// ---------------- helpers ----------------
__device__ __forceinline__ uint32_t smem_u32(const void* p) {
    uint32_t a;
    asm("{ .reg .u64 t; cvta.to.shared.u64 t, %1; cvt.u32.u64 %0, t; }" : "=r"(a) : "l"(p));
    return a;
}
__device__ __forceinline__ void mma16816(float* c, const uint32_t* a, const uint32_t* b) {
    asm volatile(
        "mma.sync.aligned.m16n8k16.row.col.f32.bf16.bf16.f32 "
        "{%0,%1,%2,%3}, {%4,%5,%6,%7}, {%8,%9}, {%0,%1,%2,%3};"
        : "+f"(c[0]), "+f"(c[1]), "+f"(c[2]), "+f"(c[3])
        : "r"(a[0]), "r"(a[1]), "r"(a[2]), "r"(a[3]), "r"(b[0]), "r"(b[1]));
}
__device__ __forceinline__ void ldmx4(uint32_t* r, uint32_t addr) {
    asm volatile("ldmatrix.sync.aligned.m8n8.x4.shared.b16 {%0,%1,%2,%3}, [%4];"
                 : "=r"(r[0]), "=r"(r[1]), "=r"(r[2]), "=r"(r[3]) : "r"(addr));
}
__device__ __forceinline__ void ldmx2t(uint32_t* r, uint32_t addr) {
    asm volatile("ldmatrix.sync.aligned.m8n8.x2.trans.shared.b16 {%0,%1}, [%2];"
                 : "=r"(r[0]), "=r"(r[1]) : "r"(addr));
}
__device__ __forceinline__ void cpasync16(uint32_t saddr, const void* gaddr, uint32_t sz) {
    asm volatile("cp.async.ca.shared.global [%0], [%1], 16, %2;"
                 :: "r"(saddr), "l"(gaddr), "r"(sz));
}
__device__ __forceinline__ uint32_t pack_hi(float v0, float v1, float& r0, float& r1) {
    __nv_bfloat16 h0 = __float2bfloat16_rn(v0);
    __nv_bfloat16 h1 = __float2bfloat16_rn(v1);
    r0 = v0 - __bfloat162float(h0);
    r1 = v1 - __bfloat162float(h1);
    __nv_bfloat162 p = __halves2bfloat162(h0, h1);
    return *(uint32_t*)&p;
}

// ---------------- CSR build ----------------
__global__ void k_zero_counts() {
    int i = blockIdx.x * blockDim.x + threadIdx.x;
    if (i < NN) g_counts[i] = 0;
}
__global__ void k_hist(const int* __restrict__ dst) {
    int e = blockIdx.x * blockDim.x + threadIdx.x;
    if (e < EE) atomicAdd(&g_counts[dst[e]], 1);
}
__global__ void k_scan1() {
    __shared__ int sh[1024];
    int tid = threadIdx.x;
    int i = blockIdx.x * 1024 + tid;
    int v = (i < NN) ? g_counts[i] : 0;
    sh[tid] = v;
    __syncthreads();
    for (int off = 1; off < 1024; off <<= 1) {
        int t = (tid >= off) ? sh[tid - off] : 0;
        __syncthreads();
        sh[tid] += t;
        __syncthreads();
    }
    if (i < NN) g_rowptr[i + 1] = sh[tid];
    if (tid == 1023) g_bsums[blockIdx.x] = sh[tid];
}
__global__ void k_scan2(int nb) {
    __shared__ int sh[128];
    int tid = threadIdx.x;
    int v = (tid < nb) ? g_bsums[tid] : 0;
    sh[tid] = v;
    __syncthreads();
    for (int off = 1; off < 128; off <<= 1) {
        int t = (tid >= off) ? sh[tid - off] : 0;
        __syncthreads();
        sh[tid] += t;
        __syncthreads();
    }
    if (tid < nb) g_bsums[tid] = sh[tid] - v;
}
// finalize rowptr AND set write cursors (counts[i] = rowptr[i]) in one pass
__global__ void k_scan3() {
    int i = blockIdx.x * 1024 + threadIdx.x;
    if (i < NN) {
        int inc = g_rowptr[i + 1] + g_bsums[blockIdx.x];
        g_rowptr[i + 1] = inc;
        g_counts[i] = inc - g_counts[i];   // exclusive prefix = rowptr[i]
    }
    if (i == 0) g_rowptr[0] = 0;
}
__global__ void k_scatter(const int* __restrict__ src, const int* __restrict__ dst) {
    int e = blockIdx.x * blockDim.x + threadIdx.x;
    if (e < EE) {
        int p = atomicAdd(&g_counts[dst[e]], 1);
        g_esrc[p] = src[e];
    }
}

// ---------------- weight convert ----------------
__global__ void k_wconv(const float* __restrict__ W, int K,
                        __nv_bfloat16* __restrict__ hi, __nv_bfloat16* __restrict__ lo) {
    int idx = blockIdx.x * blockDim.x + threadIdx.x;
    if (idx >= K * 256) return;
    float w = W[idx];
    __nv_bfloat16 h = __float2bfloat16_rn(w);
    hi[idx] = h;
    lo[idx] = __float2bfloat16_rn(w - __bfloat162float(h));
}

// ---------------- init output with bias (head partials atomicAdd into it) ---
__global__ void k_outinit(float* __restrict__ out, const float* __restrict__ b) {
    int i = blockIdx.x * blockDim.x + threadIdx.x;
    if (i < NN) {
        out[i * 2 + 0] = b[0];
        out[i * 2 + 1] = b[1];
    }
}

// ---------------- aggregation (round-4 proven form): thread-per-float4 ----------------
template <int FD>
__global__ void agg_kernel(const float* __restrict__ h,
                           __nv_bfloat16* __restrict__ zhi, __nv_bfloat16* __restrict__ zlo) {
    constexpr int TPN = FD / 4;          // threads per node (float4 lanes)
    constexpr int NPB = 256 / TPN;       // nodes per 256-thread block
    int local = threadIdx.x / TPN;
    int lane  = threadIdx.x % TPN;
    int node  = blockIdx.x * NPB + local;
    if (node >= NN) return;

    const float4* h4 = (const float4*)h;
    int beg = g_rowptr[node];
    int end = g_rowptr[node + 1];

    float4 acc = h4[(size_t)node * TPN + lane];
    for (int e = beg; e < end; e++) {
        int s = __ldg(&g_esrc[e]);
        float4 v = __ldg(&h4[(size_t)s * TPN + lane]);
        acc.x += v.x; acc.y += v.y; acc.z += v.z; acc.w += v.w;
    }
    float vv[4] = {acc.x, acc.y, acc.z, acc.w};
    __nv_bfloat16 hh[4], ll[4];
#pragma unroll
    for (int q = 0; q < 4; q++) {
        hh[q] = __float2bfloat16_rn(vv[q]);
        ll[q] = __float2bfloat16_rn(vv[q] - __bfloat162float(hh[q]));
    }
    size_t off = (size_t)node * FD + lane * 4;
    *(uint2*)(zhi + off) = *(uint2*)hh;
    *(uint2*)(zlo + off) = *(uint2*)ll;
}

// ---------------- mma.sync GEMM, 3-term bf16 split ----------------
// MODE 0: BN + ReLU -> bf16 hi/lo   MODE 1: bias + ReLU -> fp32
// MODE 3: bias, fused head: atomicAdd partials of row@outW into outO
static constexpr int STG_STRIDE = 32768;
static constexpr int A_LO = 8192, B_HI = 16384, B_LO = 24576;
static constexpr int SM_SCL = 65536, SM_SFT = 66560, SM_RED = 67584;
static constexpr int SMEM_BYTES = 68608;

template <int K, int MODE>
__global__ void __launch_bounds__(256, 1)
gemm_mma(const __nv_bfloat16* __restrict__ Ah, const __nv_bfloat16* __restrict__ Al,
         const __nv_bfloat16* __restrict__ Bh, const __nv_bfloat16* __restrict__ Bl,
         float* __restrict__ Cf,
         __nv_bfloat16* __restrict__ Chi, __nv_bfloat16* __restrict__ Clo,
         const float* __restrict__ bias,
         const float* __restrict__ gamma, const float* __restrict__ beta,
         const float* __restrict__ mu,    const float* __restrict__ var,
         const float* __restrict__ woW, float* __restrict__ outO) {
    extern __shared__ char sc[];
    uint32_t sb = smem_u32(sc);
    constexpr int NST = K / 32;

    int tid = threadIdx.x;
    int wid = tid >> 5;
    int lane = tid & 31;
    int wm = wid >> 2;
    int wn = wid & 3;
    int n0 = blockIdx.x * 128;
    int m0 = blockIdx.y * 128;

    if (tid < 256) {
        float s, t;
        if (MODE == 0) {
            float iv = rsqrtf(var[tid] + BN_EPS);
            s = gamma[tid] * iv;
            t = (bias[tid] - mu[tid]) * s + beta[tid];
        } else {
            s = 1.f;
            t = bias[tid];
        }
        ((float*)(sc + SM_SCL))[tid] = s;
        ((float*)(sc + SM_SFT))[tid] = t;
    }

    auto load_stage = [&](int s) {
        int buf = s & 1;
        uint32_t ss = sb + buf * STG_STRIDE;
        int k0 = s * 32;
#pragma unroll
        for (int r = 0; r < 2; r++) {
            int idx = tid + r * 256;
            int m = idx >> 2, c = idx & 3;
            uint32_t phys = m * 64 + ((c ^ ((m >> 1) & 3)) * 16);
            int gm = m0 + m;
            uint32_t sz = (gm < NN) ? 16u : 0u;
            size_t go = (size_t)(gm < NN ? gm : 0) * K + k0 + c * 8;
            cpasync16(ss + phys,        Ah + go, sz);
            cpasync16(ss + A_LO + phys, Al + go, sz);
        }
#pragma unroll
        for (int r = 0; r < 2; r++) {
            int idx = tid + r * 256;
            int kk = idx >> 4, j = idx & 15;
            uint32_t phys = kk * 256 + ((j ^ (kk & 7)) * 16);
            size_t go = (size_t)(k0 + kk) * 256 + n0 + j * 8;
            cpasync16(ss + B_HI + phys, Bh + go, 16);
            cpasync16(ss + B_LO + phys, Bl + go, 16);
        }
        asm volatile("cp.async.commit_group;" ::: "memory");
    };

    int ml = lane & 15, chalf = lane >> 4;
    uint32_t a_off[4];
    int a_sw[4];
#pragma unroll
    for (int t = 0; t < 4; t++) {
        int mrow = wm * 64 + t * 16 + ml;
        a_off[t] = mrow * 64;
        a_sw[t] = (mrow >> 1) & 3;
    }
    uint32_t b_off[4];
#pragma unroll
    for (int u = 0; u < 4; u++) {
        int j = wn * 4 + u;
        b_off[u] = (lane & 15) * 256 + ((j ^ (lane & 7)) * 16);
    }

    float acc[4][4][4];
#pragma unroll
    for (int t = 0; t < 4; t++)
#pragma unroll
        for (int u = 0; u < 4; u++)
#pragma unroll
            for (int r = 0; r < 4; r++) acc[t][u][r] = 0.f;

    load_stage(0);
    load_stage(1);

    for (int s = 0; s < NST; s++) {
        if (s + 1 < NST) asm volatile("cp.async.wait_group 1;" ::: "memory");
        else             asm volatile("cp.async.wait_group 0;" ::: "memory");
        __syncthreads();

        uint32_t ss = sb + (s & 1) * STG_STRIDE;
#pragma unroll
        for (int ks = 0; ks < 2; ks++) {
            uint32_t ah[4][4], al[4][4], bh[4][2], bl[4][2];
#pragma unroll
            for (int t = 0; t < 4; t++) {
                uint32_t co = (uint32_t)(((ks * 2 + chalf) ^ a_sw[t]) * 16);
                ldmx4(ah[t], ss + a_off[t] + co);
                ldmx4(al[t], ss + A_LO + a_off[t] + co);
            }
#pragma unroll
            for (int u = 0; u < 4; u++) {
                ldmx2t(bh[u], ss + B_HI + b_off[u] + ks * 4096);
                ldmx2t(bl[u], ss + B_LO + b_off[u] + ks * 4096);
            }
#pragma unroll
            for (int t = 0; t < 4; t++)
#pragma unroll
                for (int u = 0; u < 4; u++) {
                    mma16816(acc[t][u], ah[t], bh[u]);
                    mma16816(acc[t][u], ah[t], bl[u]);
                    mma16816(acc[t][u], al[t], bh[u]);
                }
        }
        __syncthreads();
        if (s + 2 < NST) load_stage(s + 2);
    }

    // -------- epilogue --------
    const float* scl = (const float*)(sc + SM_SCL);
    const float* sft = (const float*)(sc + SM_SFT);
    int g = lane >> 2, tg = lane & 3;

    if (MODE == 3) {
        float* red = (float*)(sc + SM_RED);
        red[tid] = 0.f;           // 256 floats = 128 rows x 2 outputs
        __syncthreads();
#pragma unroll
        for (int t = 0; t < 4; t++) {
#pragma unroll
            for (int half = 0; half < 2; half++) {
                int rl = wm * 64 + t * 16 + g + half * 8;
                float p0 = 0.f, p1 = 0.f;
#pragma unroll
                for (int u = 0; u < 4; u++) {
                    int col = n0 + wn * 32 + u * 8 + tg * 2;
                    float v0 = acc[t][u][half * 2 + 0] + sft[col];
                    float v1 = acc[t][u][half * 2 + 1] + sft[col + 1];
                    float w00 = __ldg(&woW[col * 2 + 0]),       w01 = __ldg(&woW[col * 2 + 1]);
                    float w10 = __ldg(&woW[(col + 1) * 2 + 0]), w11 = __ldg(&woW[(col + 1) * 2 + 1]);
                    p0 += v0 * w00 + v1 * w10;
                    p1 += v0 * w01 + v1 * w11;
                }
                atomicAdd(&red[rl * 2 + 0], p0);
                atomicAdd(&red[rl * 2 + 1], p1);
            }
        }
        __syncthreads();
        if (tid < 128) {
            int row = m0 + tid;
            if (row < NN) {
                atomicAdd(&outO[(size_t)row * 2 + 0], red[tid * 2 + 0]);
                atomicAdd(&outO[(size_t)row * 2 + 1], red[tid * 2 + 1]);
            }
        }
        return;
    }

#pragma unroll
    for (int t = 0; t < 4; t++) {
        int row0 = m0 + wm * 64 + t * 16 + g;
#pragma unroll
        for (int u = 0; u < 4; u++) {
            int col = n0 + wn * 32 + u * 8 + tg * 2;
            float s0 = scl[col], s1 = scl[col + 1];
            float f0 = sft[col], f1 = sft[col + 1];
#pragma unroll
            for (int half = 0; half < 2; half++) {
                int row = row0 + half * 8;
                if (row >= NN) continue;
                float v0 = acc[t][u][half * 2 + 0] * s0 + f0;
                float v1 = acc[t][u][half * 2 + 1] * s1 + f1;
                v0 = fmaxf(v0, 0.f); v1 = fmaxf(v1, 0.f);
                size_t o = (size_t)row * 256 + col;
                if (MODE == 0) {
                    float r0, r1;
                    uint32_t hp = pack_hi(v0, v1, r0, r1);
                    __nv_bfloat162 lp2 = __halves2bfloat162(
                        __float2bfloat16_rn(r0), __float2bfloat16_rn(r1));
                    *(uint32_t*)(Chi + o) = hp;
                    *(uint32_t*)(Clo + o) = *(uint32_t*)&lp2;
                } else {
                    *(float2*)(Cf + o) = make_float2(v0, v1);
                }
            }
        }
    }
}

// ---------------- launch ----------------
extern "C" void kernel_launch(void* const* d_in, const int* in_sizes, int n_in,
                              void* d_out, int out_size) {
    const float* x  = (const float*)d_in[0];
    const int*   ei = (const int*)d_in[1];
    const int* src = ei;
    const int* dst = ei + EE;

    const float* L[3][8];
    for (int l = 0; l < 3; l++)
        for (int p = 0; p < 8; p++)
            L[l][p] = (const float*)d_in[2 + l * 8 + p];
    const float* out_W = (const float*)d_in[26];
    const float* out_b = (const float*)d_in[27];

    __nv_bfloat16 *zhi, *zlo, *thi, *tlo, *wt;
    float *hA, *hB;
    cudaGetSymbolAddress((void**)&zhi, g_zhi);
    cudaGetSymbolAddress((void**)&zlo, g_zlo);
    cudaGetSymbolAddress((void**)&thi, g_thi);
    cudaGetSymbolAddress((void**)&tlo, g_tlo);
    cudaGetSymbolAddress((void**)&hA,  g_hA);
    cudaGetSymbolAddress((void**)&hB,  g_hB);
    cudaGetSymbolAddress((void**)&wt,  g_w);
    auto WT = [&](int w, int hl) { return wt + ((size_t)w * 2 + hl) * HDIM * HDIM; };

    static bool inited = false;
    static cudaStream_t sA, sB;
    static cudaEvent_t ev[4];
    if (!inited) {
        inited = true;
        cudaStreamCreateWithFlags(&sA, cudaStreamNonBlocking);
        cudaStreamCreateWithFlags(&sB, cudaStreamNonBlocking);
        for (int i = 0; i < 4; i++) cudaEventCreateWithFlags(&ev[i], cudaEventDisableTiming);
        cudaFuncSetAttribute(gemm_mma<128, 0>, cudaFuncAttributeMaxDynamicSharedMemorySize, SMEM_BYTES);
        cudaFuncSetAttribute(gemm_mma<256, 0>, cudaFuncAttributeMaxDynamicSharedMemorySize, SMEM_BYTES);
        cudaFuncSetAttribute(gemm_mma<256, 1>, cudaFuncAttributeMaxDynamicSharedMemorySize, SMEM_BYTES);
        cudaFuncSetAttribute(gemm_mma<256, 3>, cudaFuncAttributeMaxDynamicSharedMemorySize, SMEM_BYTES);
    }

    // ---- prologue fork: CSR (sA) || weight conv + out init (sB) ----
    cudaEventRecord(ev[0], 0);
    cudaStreamWaitEvent(sA, ev[0], 0);
    cudaStreamWaitEvent(sB, ev[0], 0);

    int nb_scan = (NN + 1023) / 1024;
    k_zero_counts<<<(NN + 255) / 256, 256, 0, sA>>>();
    k_hist<<<(EE + 255) / 256, 256, 0, sA>>>(dst);
    k_scan1<<<nb_scan, 1024, 0, sA>>>();
    k_scan2<<<1, 128, 0, sA>>>(nb_scan);
    k_scan3<<<nb_scan, 1024, 0, sA>>>();
    k_scatter<<<(EE + 255) / 256, 256, 0, sA>>>(src, dst);

    k_wconv<<<(128 * 256 + 255) / 256, 256, 0, sB>>>(L[0][0], 128, WT(0, 0), WT(0, 1));
    k_wconv<<<(256 * 256 + 255) / 256, 256, 0, sB>>>(L[0][6], 256, WT(1, 0), WT(1, 1));
    k_wconv<<<(256 * 256 + 255) / 256, 256, 0, sB>>>(L[1][0], 256, WT(2, 0), WT(2, 1));
    k_wconv<<<(256 * 256 + 255) / 256, 256, 0, sB>>>(L[1][6], 256, WT(3, 0), WT(3, 1));
    k_wconv<<<(256 * 256 + 255) / 256, 256, 0, sB>>>(L[2][0], 256, WT(4, 0), WT(4, 1));
    k_wconv<<<(256 * 256 + 255) / 256, 256, 0, sB>>>(L[2][6], 256, WT(5, 0), WT(5, 1));
    k_outinit<<<(NN + 255) / 256, 256, 0, sB>>>((float*)d_out, out_b);

    // join to stream 0
    cudaEventRecord(ev[1], sA);
    cudaEventRecord(ev[2], sB);
    cudaStreamWaitEvent(0, ev[1], 0);
    cudaStreamWaitEvent(0, ev[2], 0);

    dim3 gg(2, (NN + 127) / 128);

    // ---- layer 1 ----
    agg_kernel<128><<<(NN + 7) / 8, 256>>>(x, zhi, zlo);
    gemm_mma<128, 0><<<gg, 256, SMEM_BYTES>>>(zhi, zlo, WT(0, 0), WT(0, 1),
        nullptr, thi, tlo, L[0][1], L[0][2], L[0][3], L[0][4], L[0][5], nullptr, nullptr);
    gemm_mma<256, 1><<<gg, 256, SMEM_BYTES>>>(thi, tlo, WT(1, 0), WT(1, 1),
        hA, nullptr, nullptr, L[0][7], nullptr, nullptr, nullptr, nullptr, nullptr, nullptr);

    // ---- layer 2 ----
    agg_kernel<256><<<(NN + 3) / 4, 256>>>(hA, zhi, zlo);
    gemm_mma<256, 0><<<gg, 256, SMEM_BYTES>>>(zhi, zlo, WT(2, 0), WT(2, 1),
        nullptr, thi, tlo, L[1][1], L[1][2], L[1][3], L[1][4], L[1][5], nullptr, nullptr);
    gemm_mma<256, 1><<<gg, 256, SMEM_BYTES>>>(thi, tlo, WT(3, 0), WT(3, 1),
        hB, nullptr, nullptr, L[1][7], nullptr, nullptr, nullptr, nullptr, nullptr, nullptr);

    // ---- layer 3 + fused head ----
    agg_kernel<256><<<(NN + 3) / 4, 256>>>(hB, zhi, zlo);
    gemm_mma<256, 0><<<gg, 256, SMEM_BYTES>>>(zhi, zlo, WT(4, 0), WT(4, 1),
        nullptr, thi, tlo, L[2][1], L[2][2], L[2][3], L[2][4], L[2][5], nullptr, nullptr);
    gemm_mma<256, 3><<<gg, 256, SMEM_BYTES>>>(thi, tlo, WT(5, 0), WT(5, 1),
        nullptr, nullptr, nullptr, L[2][7], nullptr, nullptr, nullptr, nullptr,
        out_W, (float*)d_out);
}

// round 12
// speedup vs baseline: 1.4665x; 1.4665x over previous
#include <cuda_runtime.h>
#include <cuda_bf16.h>
#include <cstdint>
#include <math.h>

#define NN 100000
#define EE 3200000
#define HDIM 256
#define BN_EPS 1e-5f

// ---------------- device scratch ----------------
__device__ __nv_bfloat16 g_zhi[(size_t)NN * HDIM];
__device__ __nv_bfloat16 g_zlo[(size_t)NN * HDIM];
__device__ __nv_bfloat16 g_thi[(size_t)NN * HDIM];
__device__ __nv_bfloat16 g_tlo[(size_t)NN * HDIM];
__device__ float         g_hA [(size_t)NN * HDIM];
__device__ float         g_hB [(size_t)NN * HDIM];
__device__ __nv_bfloat16 g_w  [6][2][HDIM * HDIM];   // W [K][256] bf16 hi/lo (k-major)
__device__ int g_counts[NN];
__device__ int g_rowptr[NN + 1];
__device__ int g_esrc[EE];
__device__ int g_bsums[128];

// ---------------- helpers ----------------
__device__ __forceinline__ uint32_t smem_u32(const void* p) {
    uint32_t a;
    asm("{ .reg .u64 t; cvta.to.shared.u64 t, %1; cvt.u32.u64 %0, t; }" : "=r"(a) : "l"(p));
    return a;
}
__device__ __forceinline__ void mma16816(float* c, const uint32_t* a, const uint32_t* b) {
    asm volatile(
        "mma.sync.aligned.m16n8k16.row.col.f32.bf16.bf16.f32 "
        "{%0,%1,%2,%3}, {%4,%5,%6,%7}, {%8,%9}, {%0,%1,%2,%3};"
        : "+f"(c[0]), "+f"(c[1]), "+f"(c[2]), "+f"(c[3])
        : "r"(a[0]), "r"(a[1]), "r"(a[2]), "r"(a[3]), "r"(b[0]), "r"(b[1]));
}
__device__ __forceinline__ void ldmx4(uint32_t* r, uint32_t addr) {
    asm volatile("ldmatrix.sync.aligned.m8n8.x4.shared.b16 {%0,%1,%2,%3}, [%4];"
                 : "=r"(r[0]), "=r"(r[1]), "=r"(r[2]), "=r"(r[3]) : "r"(addr));
}
__device__ __forceinline__ void ldmx2t(uint32_t* r, uint32_t addr) {
    asm volatile("ldmatrix.sync.aligned.m8n8.x2.trans.shared.b16 {%0,%1}, [%2];"
                 : "=r"(r[0]), "=r"(r[1]) : "r"(addr));
}
__device__ __forceinline__ void cpasync16(uint32_t saddr, const void* gaddr, uint32_t sz) {
    asm volatile("cp.async.ca.shared.global [%0], [%1], 16, %2;"
                 :: "r"(saddr), "l"(gaddr), "r"(sz));
}
__device__ __forceinline__ uint32_t pack_hi(float v0, float v1, float& r0, float& r1) {
    __nv_bfloat16 h0 = __float2bfloat16_rn(v0);
    __nv_bfloat16 h1 = __float2bfloat16_rn(v1);
    r0 = v0 - __bfloat162float(h0);
    r1 = v1 - __bfloat162float(h1);
    __nv_bfloat162 p = __halves2bfloat162(h0, h1);
    return *(uint32_t*)&p;
}

// ---------------- CSR build ----------------
__global__ void k_zero_counts() {
    int i = blockIdx.x * blockDim.x + threadIdx.x;
    if (i < NN) g_counts[i] = 0;
}
__global__ void k_hist(const int* __restrict__ dst) {
    int e = blockIdx.x * blockDim.x + threadIdx.x;
    if (e < EE) atomicAdd(&g_counts[dst[e]], 1);
}
__global__ void k_scan1() {
    __shared__ int sh[1024];
    int tid = threadIdx.x;
    int i = blockIdx.x * 1024 + tid;
    int v = (i < NN) ? g_counts[i] : 0;
    sh[tid] = v;
    __syncthreads();
    for (int off = 1; off < 1024; off <<= 1) {
        int t = (tid >= off) ? sh[tid - off] : 0;
        __syncthreads();
        sh[tid] += t;
        __syncthreads();
    }
    if (i < NN) g_rowptr[i + 1] = sh[tid];
    if (tid == 1023) g_bsums[blockIdx.x] = sh[tid];
}
__global__ void k_scan2(int nb) {
    __shared__ int sh[128];
    int tid = threadIdx.x;
    int v = (tid < nb) ? g_bsums[tid] : 0;
    sh[tid] = v;
    __syncthreads();
    for (int off = 1; off < 128; off <<= 1) {
        int t = (tid >= off) ? sh[tid - off] : 0;
        __syncthreads();
        sh[tid] += t;
        __syncthreads();
    }
    if (tid < nb) g_bsums[tid] = sh[tid] - v;
}
// finalize rowptr AND set write cursors (counts[i] = rowptr[i]) in one pass
__global__ void k_scan3() {
    int i = blockIdx.x * 1024 + threadIdx.x;
    if (i < NN) {
        int inc = g_rowptr[i + 1] + g_bsums[blockIdx.x];
        g_rowptr[i + 1] = inc;
        g_counts[i] = inc - g_counts[i];   // exclusive prefix = rowptr[i]
    }
    if (i == 0) g_rowptr[0] = 0;
}
__global__ void k_scatter(const int* __restrict__ src, const int* __restrict__ dst) {
    int e = blockIdx.x * blockDim.x + threadIdx.x;
    if (e < EE) {
        int p = atomicAdd(&g_counts[dst[e]], 1);
        g_esrc[p] = src[e];
    }
}

// ---------------- weight convert ----------------
__global__ void k_wconv(const float* __restrict__ W, int K,
                        __nv_bfloat16* __restrict__ hi, __nv_bfloat16* __restrict__ lo) {
    int idx = blockIdx.x * blockDim.x + threadIdx.x;
    if (idx >= K * 256) return;
    float w = W[idx];
    __nv_bfloat16 h = __float2bfloat16_rn(w);
    hi[idx] = h;
    lo[idx] = __float2bfloat16_rn(w - __bfloat162float(h));
}

// ---------------- init output with bias (head partials atomicAdd into it) ---
__global__ void k_outinit(float* __restrict__ out, const float* __restrict__ b) {
    int i = blockIdx.x * blockDim.x + threadIdx.x;
    if (i < NN) {
        out[i * 2 + 0] = b[0];
        out[i * 2 + 1] = b[1];
    }
}

// ---------------- aggregation (round-4 proven form): thread-per-float4 ----------------
template <int FD>
__global__ void agg_kernel(const float* __restrict__ h,
                           __nv_bfloat16* __restrict__ zhi, __nv_bfloat16* __restrict__ zlo) {
    constexpr int TPN = FD / 4;          // threads per node (float4 lanes)
    constexpr int NPB = 256 / TPN;       // nodes per 256-thread block
    int local = threadIdx.x / TPN;
    int lane  = threadIdx.x % TPN;
    int node  = blockIdx.x * NPB + local;
    if (node >= NN) return;

    const float4* h4 = (const float4*)h;
    int beg = g_rowptr[node];
    int end = g_rowptr[node + 1];

    float4 acc = h4[(size_t)node * TPN + lane];
    for (int e = beg; e < end; e++) {
        int s = g_esrc[e];
        float4 v = __ldg(&h4[(size_t)s * TPN + lane]);
        acc.x += v.x; acc.y += v.y; acc.z += v.z; acc.w += v.w;
    }
    float vv[4] = {acc.x, acc.y, acc.z, acc.w};
    __nv_bfloat16 hh[4], ll[4];
#pragma unroll
    for (int q = 0; q < 4; q++) {
        hh[q] = __float2bfloat16_rn(vv[q]);
        ll[q] = __float2bfloat16_rn(vv[q] - __bfloat162float(hh[q]));
    }
    size_t off = (size_t)node * FD + lane * 4;
    *(uint2*)(zhi + off) = *(uint2*)hh;
    *(uint2*)(zlo + off) = *(uint2*)ll;
}

// ---------------- mma.sync GEMM, 3-term bf16 split ----------------
// MODE 0: BN + ReLU -> bf16 hi/lo   MODE 1: bias + ReLU -> fp32
// MODE 3: bias, fused head: atomicAdd partials of row@outW into outO
static constexpr int STG_STRIDE = 32768;
static constexpr int A_LO = 8192, B_HI = 16384, B_LO = 24576;
static constexpr int SM_SCL = 65536, SM_SFT = 66560, SM_RED = 67584;
static constexpr int SMEM_BYTES = 68608;

template <int K, int MODE>
__global__ void __launch_bounds__(256, 1)
gemm_mma(const __nv_bfloat16* __restrict__ Ah, const __nv_bfloat16* __restrict__ Al,
         const __nv_bfloat16* __restrict__ Bh, const __nv_bfloat16* __restrict__ Bl,
         float* __restrict__ Cf,
         __nv_bfloat16* __restrict__ Chi, __nv_bfloat16* __restrict__ Clo,
         const float* __restrict__ bias,
         const float* __restrict__ gamma, const float* __restrict__ beta,
         const float* __restrict__ mu,    const float* __restrict__ var,
         const float* __restrict__ woW, float* __restrict__ outO) {
    extern __shared__ char sc[];
    uint32_t sb = smem_u32(sc);
    constexpr int NST = K / 32;

    int tid = threadIdx.x;
    int wid = tid >> 5;
    int lane = tid & 31;
    int wm = wid >> 2;
    int wn = wid & 3;
    int n0 = blockIdx.x * 128;
    int m0 = blockIdx.y * 128;

    if (tid < 256) {
        float s, t;
        if (MODE == 0) {
            float iv = rsqrtf(var[tid] + BN_EPS);
            s = gamma[tid] * iv;
            t = (bias[tid] - mu[tid]) * s + beta[tid];
        } else {
            s = 1.f;
            t = bias[tid];
        }
        ((float*)(sc + SM_SCL))[tid] = s;
        ((float*)(sc + SM_SFT))[tid] = t;
    }

    auto load_stage = [&](int s) {
        int buf = s & 1;
        uint32_t ss = sb + buf * STG_STRIDE;
        int k0 = s * 32;
#pragma unroll
        for (int r = 0; r < 2; r++) {
            int idx = tid + r * 256;
            int m = idx >> 2, c = idx & 3;
            uint32_t phys = m * 64 + ((c ^ ((m >> 1) & 3)) * 16);
            int gm = m0 + m;
            uint32_t sz = (gm < NN) ? 16u : 0u;
            size_t go = (size_t)(gm < NN ? gm : 0) * K + k0 + c * 8;
            cpasync16(ss + phys,        Ah + go, sz);
            cpasync16(ss + A_LO + phys, Al + go, sz);
        }
#pragma unroll
        for (int r = 0; r < 2; r++) {
            int idx = tid + r * 256;
            int kk = idx >> 4, j = idx & 15;
            uint32_t phys = kk * 256 + ((j ^ (kk & 7)) * 16);
            size_t go = (size_t)(k0 + kk) * 256 + n0 + j * 8;
            cpasync16(ss + B_HI + phys, Bh + go, 16);
            cpasync16(ss + B_LO + phys, Bl + go, 16);
        }
        asm volatile("cp.async.commit_group;" ::: "memory");
    };

    int ml = lane & 15, chalf = lane >> 4;
    uint32_t a_off[4];
    int a_sw[4];
#pragma unroll
    for (int t = 0; t < 4; t++) {
        int mrow = wm * 64 + t * 16 + ml;
        a_off[t] = mrow * 64;
        a_sw[t] = (mrow >> 1) & 3;
    }
    uint32_t b_off[4];
#pragma unroll
    for (int u = 0; u < 4; u++) {
        int j = wn * 4 + u;
        b_off[u] = (lane & 15) * 256 + ((j ^ (lane & 7)) * 16);
    }

    float acc[4][4][4];
#pragma unroll
    for (int t = 0; t < 4; t++)
#pragma unroll
        for (int u = 0; u < 4; u++)
#pragma unroll
            for (int r = 0; r < 4; r++) acc[t][u][r] = 0.f;

    load_stage(0);
    load_stage(1);

    for (int s = 0; s < NST; s++) {
        if (s + 1 < NST) asm volatile("cp.async.wait_group 1;" ::: "memory");
        else             asm volatile("cp.async.wait_group 0;" ::: "memory");
        __syncthreads();

        uint32_t ss = sb + (s & 1) * STG_STRIDE;
#pragma unroll
        for (int ks = 0; ks < 2; ks++) {
            uint32_t ah[4][4], al[4][4], bh[4][2], bl[4][2];
#pragma unroll
            for (int t = 0; t < 4; t++) {
                uint32_t co = (uint32_t)(((ks * 2 + chalf) ^ a_sw[t]) * 16);
                ldmx4(ah[t], ss + a_off[t] + co);
                ldmx4(al[t], ss + A_LO + a_off[t] + co);
            }
#pragma unroll
            for (int u = 0; u < 4; u++) {
                ldmx2t(bh[u], ss + B_HI + b_off[u] + ks * 4096);
                ldmx2t(bl[u], ss + B_LO + b_off[u] + ks * 4096);
            }
#pragma unroll
            for (int t = 0; t < 4; t++)
#pragma unroll
                for (int u = 0; u < 4; u++) {
                    mma16816(acc[t][u], ah[t], bh[u]);
                    mma16816(acc[t][u], ah[t], bl[u]);
                    mma16816(acc[t][u], al[t], bh[u]);
                }
        }
        __syncthreads();
        if (s + 2 < NST) load_stage(s + 2);
    }

    // -------- epilogue --------
    const float* scl = (const float*)(sc + SM_SCL);
    const float* sft = (const float*)(sc + SM_SFT);
    int g = lane >> 2, tg = lane & 3;

    if (MODE == 3) {
        float* red = (float*)(sc + SM_RED);
        red[tid] = 0.f;           // 256 floats = 128 rows x 2 outputs
        __syncthreads();
#pragma unroll
        for (int t = 0; t < 4; t++) {
#pragma unroll
            for (int half = 0; half < 2; half++) {
                int rl = wm * 64 + t * 16 + g + half * 8;
                float p0 = 0.f, p1 = 0.f;
#pragma unroll
                for (int u = 0; u < 4; u++) {
                    int col = n0 + wn * 32 + u * 8 + tg * 2;
                    float v0 = acc[t][u][half * 2 + 0] + sft[col];
                    float v1 = acc[t][u][half * 2 + 1] + sft[col + 1];
                    float w00 = __ldg(&woW[col * 2 + 0]),       w01 = __ldg(&woW[col * 2 + 1]);
                    float w10 = __ldg(&woW[(col + 1) * 2 + 0]), w11 = __ldg(&woW[(col + 1) * 2 + 1]);
                    p0 += v0 * w00 + v1 * w10;
                    p1 += v0 * w01 + v1 * w11;
                }
                atomicAdd(&red[rl * 2 + 0], p0);
                atomicAdd(&red[rl * 2 + 1], p1);
            }
        }
        __syncthreads();
        if (tid < 128) {
            int row = m0 + tid;
            if (row < NN) {
                atomicAdd(&outO[(size_t)row * 2 + 0], red[tid * 2 + 0]);
                atomicAdd(&outO[(size_t)row * 2 + 1], red[tid * 2 + 1]);
            }
        }
        return;
    }

#pragma unroll
    for (int t = 0; t < 4; t++) {
        int row0 = m0 + wm * 64 + t * 16 + g;
#pragma unroll
        for (int u = 0; u < 4; u++) {
            int col = n0 + wn * 32 + u * 8 + tg * 2;
            float s0 = scl[col], s1 = scl[col + 1];
            float f0 = sft[col], f1 = sft[col + 1];
#pragma unroll
            for (int half = 0; half < 2; half++) {
                int row = row0 + half * 8;
                if (row >= NN) continue;
                float v0 = acc[t][u][half * 2 + 0] * s0 + f0;
                float v1 = acc[t][u][half * 2 + 1] * s1 + f1;
                v0 = fmaxf(v0, 0.f); v1 = fmaxf(v1, 0.f);
                size_t o = (size_t)row * 256 + col;
                if (MODE == 0) {
                    float r0, r1;
                    uint32_t hp = pack_hi(v0, v1, r0, r1);
                    __nv_bfloat162 lp2 = __halves2bfloat162(
                        __float2bfloat16_rn(r0), __float2bfloat16_rn(r1));
                    *(uint32_t*)(Chi + o) = hp;
                    *(uint32_t*)(Clo + o) = *(uint32_t*)&lp2;
                } else {
                    *(float2*)(Cf + o) = make_float2(v0, v1);
                }
            }
        }
    }
}

// ---------------- launch: fully serial on the default stream ----------------
extern "C" void kernel_launch(void* const* d_in, const int* in_sizes, int n_in,
                              void* d_out, int out_size) {
    const float* x  = (const float*)d_in[0];
    const int*   ei = (const int*)d_in[1];
    const int* src = ei;
    const int* dst = ei + EE;

    const float* L[3][8];
    for (int l = 0; l < 3; l++)
        for (int p = 0; p < 8; p++)
            L[l][p] = (const float*)d_in[2 + l * 8 + p];
    const float* out_W = (const float*)d_in[26];
    const float* out_b = (const float*)d_in[27];

    __nv_bfloat16 *zhi, *zlo, *thi, *tlo, *wt;
    float *hA, *hB;
    cudaGetSymbolAddress((void**)&zhi, g_zhi);
    cudaGetSymbolAddress((void**)&zlo, g_zlo);
    cudaGetSymbolAddress((void**)&thi, g_thi);
    cudaGetSymbolAddress((void**)&tlo, g_tlo);
    cudaGetSymbolAddress((void**)&hA,  g_hA);
    cudaGetSymbolAddress((void**)&hB,  g_hB);
    cudaGetSymbolAddress((void**)&wt,  g_w);
    auto WT = [&](int w, int hl) { return wt + ((size_t)w * 2 + hl) * HDIM * HDIM; };

    cudaFuncSetAttribute(gemm_mma<128, 0>, cudaFuncAttributeMaxDynamicSharedMemorySize, SMEM_BYTES);
    cudaFuncSetAttribute(gemm_mma<256, 0>, cudaFuncAttributeMaxDynamicSharedMemorySize, SMEM_BYTES);
    cudaFuncSetAttribute(gemm_mma<256, 1>, cudaFuncAttributeMaxDynamicSharedMemorySize, SMEM_BYTES);
    cudaFuncSetAttribute(gemm_mma<256, 3>, cudaFuncAttributeMaxDynamicSharedMemorySize, SMEM_BYTES);

    // ---- weight conversion + output init ----
    k_wconv<<<(128 * 256 + 255) / 256, 256>>>(L[0][0], 128, WT(0, 0), WT(0, 1));
    k_wconv<<<(256 * 256 + 255) / 256, 256>>>(L[0][6], 256, WT(1, 0), WT(1, 1));
    k_wconv<<<(256 * 256 + 255) / 256, 256>>>(L[1][0], 256, WT(2, 0), WT(2, 1));
    k_wconv<<<(256 * 256 + 255) / 256, 256>>>(L[1][6], 256, WT(3, 0), WT(3, 1));
    k_wconv<<<(256 * 256 + 255) / 256, 256>>>(L[2][0], 256, WT(4, 0), WT(4, 1));
    k_wconv<<<(256 * 256 + 255) / 256, 256>>>(L[2][6], 256, WT(5, 0), WT(5, 1));
    k_outinit<<<(NN + 255) / 256, 256>>>((float*)d_out, out_b);

    // ---- CSR build ----
    int nb_scan = (NN + 1023) / 1024;
    k_zero_counts<<<(NN + 255) / 256, 256>>>();
    k_hist<<<(EE + 255) / 256, 256>>>(dst);
    k_scan1<<<nb_scan, 1024>>>();
    k_scan2<<<1, 128>>>(nb_scan);
    k_scan3<<<nb_scan, 1024>>>();
    k_scatter<<<(EE + 255) / 256, 256>>>(src, dst);

    dim3 gg(2, (NN + 127) / 128);

    // ---- layer 1 ----
    agg_kernel<128><<<(NN + 7) / 8, 256>>>(x, zhi, zlo);
    gemm_mma<128, 0><<<gg, 256, SMEM_BYTES>>>(zhi, zlo, WT(0, 0), WT(0, 1),
        nullptr, thi, tlo, L[0][1], L[0][2], L[0][3], L[0][4], L[0][5], nullptr, nullptr);
    gemm_mma<256, 1><<<gg, 256, SMEM_BYTES>>>(thi, tlo, WT(1, 0), WT(1, 1),
        hA, nullptr, nullptr, L[0][7], nullptr, nullptr, nullptr, nullptr, nullptr, nullptr);

    // ---- layer 2 ----
    agg_kernel<256><<<(NN + 3) / 4, 256>>>(hA, zhi, zlo);
    gemm_mma<256, 0><<<gg, 256, SMEM_BYTES>>>(zhi, zlo, WT(2, 0), WT(2, 1),
        nullptr, thi, tlo, L[1][1], L[1][2], L[1][3], L[1][4], L[1][5], nullptr, nullptr);
    gemm_mma<256, 1><<<gg, 256, SMEM_BYTES>>>(thi, tlo, WT(3, 0), WT(3, 1),
        hB, nullptr, nullptr, L[1][7], nullptr, nullptr, nullptr, nullptr, nullptr, nullptr);

    // ---- layer 3 + fused head ----
    agg_kernel<256><<<(NN + 3) / 4, 256>>>(hB, zhi, zlo);
    gemm_mma<256, 0><<<gg, 256, SMEM_BYTES>>>(zhi, zlo, WT(4, 0), WT(4, 1),
        nullptr, thi, tlo, L[2][1], L[2][2], L[2][3], L[2][4], L[2][5], nullptr, nullptr);
    gemm_mma<256, 3><<<gg, 256, SMEM_BYTES>>>(thi, tlo, WT(5, 0), WT(5, 1),
        nullptr, nullptr, nullptr, L[2][7], nullptr, nullptr, nullptr, nullptr,
        out_W, (float*)d_out);
}

// round 14
// speedup vs baseline: 1.6364x; 1.1158x over previous
#include <cuda_runtime.h>
#include <cuda_bf16.h>
#include <cuda_fp16.h>
#include <cstdint>
#include <math.h>

#define NN 100000
#define EE 3200000
#define HDIM 256
#define BN_EPS 1e-5f

// ---------------- device scratch ----------------
__device__ __nv_bfloat16 g_zhi[(size_t)NN * HDIM];
__device__ __nv_bfloat16 g_zlo[(size_t)NN * HDIM];
__device__ __nv_bfloat16 g_thi[(size_t)NN * HDIM];
__device__ __nv_bfloat16 g_tlo[(size_t)NN * HDIM];
__device__ float         g_hA [(size_t)NN * HDIM];
__device__ float         g_hB [(size_t)NN * HDIM];
__device__ __half        g_x16 [(size_t)NN * 128];   // fp16 gather copies
__device__ __half        g_h16A[(size_t)NN * HDIM];
__device__ __half        g_h16B[(size_t)NN * HDIM];
__device__ __nv_bfloat16 g_w  [6][2][HDIM * HDIM];   // W [K][256] bf16 hi/lo (k-major)
__device__ int g_counts[NN];
__device__ int g_rowptr[NN + 1];
__device__ int g_esrc[EE];
__device__ int g_bsums[128];

// ---------------- helpers ----------------
__device__ __forceinline__ uint32_t smem_u32(const void* p) {
    uint32_t a;
    asm("{ .reg .u64 t; cvta.to.shared.u64 t, %1; cvt.u32.u64 %0, t; }" : "=r"(a) : "l"(p));
    return a;
}
__device__ __forceinline__ void mma16816(float* c, const uint32_t* a, const uint32_t* b) {
    asm volatile(
        "mma.sync.aligned.m16n8k16.row.col.f32.bf16.bf16.f32 "
        "{%0,%1,%2,%3}, {%4,%5,%6,%7}, {%8,%9}, {%0,%1,%2,%3};"
        : "+f"(c[0]), "+f"(c[1]), "+f"(c[2]), "+f"(c[3])
        : "r"(a[0]), "r"(a[1]), "r"(a[2]), "r"(a[3]), "r"(b[0]), "r"(b[1]));
}
__device__ __forceinline__ void ldmx4(uint32_t* r, uint32_t addr) {
    asm volatile("ldmatrix.sync.aligned.m8n8.x4.shared.b16 {%0,%1,%2,%3}, [%4];"
                 : "=r"(r[0]), "=r"(r[1]), "=r"(r[2]), "=r"(r[3]) : "r"(addr));
}
__device__ __forceinline__ void ldmx2t(uint32_t* r, uint32_t addr) {
    asm volatile("ldmatrix.sync.aligned.m8n8.x2.trans.shared.b16 {%0,%1}, [%2];"
                 : "=r"(r[0]), "=r"(r[1]) : "r"(addr));
}
__device__ __forceinline__ void cpasync16(uint32_t saddr, const void* gaddr, uint32_t sz) {
    asm volatile("cp.async.ca.shared.global [%0], [%1], 16, %2;"
                 :: "r"(saddr), "l"(gaddr), "r"(sz));
}
__device__ __forceinline__ uint32_t pack_hi(float v0, float v1, float& r0, float& r1) {
    __nv_bfloat16 h0 = __float2bfloat16_rn(v0);
    __nv_bfloat16 h1 = __float2bfloat16_rn(v1);
    r0 = v0 - __bfloat162float(h0);
    r1 = v1 - __bfloat162float(h1);
    __nv_bfloat162 p = __halves2bfloat162(h0, h1);
    return *(uint32_t*)&p;
}

// ---------------- CSR build ----------------
__global__ void k_zero_counts() {
    int i = blockIdx.x * blockDim.x + threadIdx.x;
    if (i < NN) g_counts[i] = 0;
}
__global__ void k_hist(const int* __restrict__ dst) {
    int e = blockIdx.x * blockDim.x + threadIdx.x;
    if (e < EE) atomicAdd(&g_counts[dst[e]], 1);
}
__global__ void k_scan1() {
    __shared__ int sh[1024];
    int tid = threadIdx.x;
    int i = blockIdx.x * 1024 + tid;
    int v = (i < NN) ? g_counts[i] : 0;
    sh[tid] = v;
    __syncthreads();
    for (int off = 1; off < 1024; off <<= 1) {
        int t = (tid >= off) ? sh[tid - off] : 0;
        __syncthreads();
        sh[tid] += t;
        __syncthreads();
    }
    if (i < NN) g_rowptr[i + 1] = sh[tid];
    if (tid == 1023) g_bsums[blockIdx.x] = sh[tid];
}
__global__ void k_scan2(int nb) {
    __shared__ int sh[128];
    int tid = threadIdx.x;
    int v = (tid < nb) ? g_bsums[tid] : 0;
    sh[tid] = v;
    __syncthreads();
    for (int off = 1; off < 128; off <<= 1) {
        int t = (tid >= off) ? sh[tid - off] : 0;
        __syncthreads();
        sh[tid] += t;
        __syncthreads();
    }
    if (tid < nb) g_bsums[tid] = sh[tid] - v;
}
// finalize rowptr AND set write cursors (counts[i] = rowptr[i]) in one pass
__global__ void k_scan3() {
    int i = blockIdx.x * 1024 + threadIdx.x;
    if (i < NN) {
        int inc = g_rowptr[i + 1] + g_bsums[blockIdx.x];
        g_rowptr[i + 1] = inc;
        g_counts[i] = inc - g_counts[i];   // exclusive prefix = rowptr[i]
    }
    if (i == 0) g_rowptr[0] = 0;
}
__global__ void k_scatter(const int* __restrict__ src, const int* __restrict__ dst) {
    int e = blockIdx.x * blockDim.x + threadIdx.x;
    if (e < EE) {
        int p = atomicAdd(&g_counts[dst[e]], 1);
        g_esrc[p] = src[e];
    }
}

// ---------------- weight convert ----------------
__global__ void k_wconv(const float* __restrict__ W, int K,
                        __nv_bfloat16* __restrict__ hi, __nv_bfloat16* __restrict__ lo) {
    int idx = blockIdx.x * blockDim.x + threadIdx.x;
    if (idx >= K * 256) return;
    float w = W[idx];
    __nv_bfloat16 h = __float2bfloat16_rn(w);
    hi[idx] = h;
    lo[idx] = __float2bfloat16_rn(w - __bfloat162float(h));
}

// ---------------- x -> fp16 copy (gather source for layer 1) ----------------
__global__ void k_xconv(const float* __restrict__ x, __half* __restrict__ x16) {
    int i = blockIdx.x * blockDim.x + threadIdx.x;
    if (i < NN * 128) x16[i] = __float2half_rn(x[i]);
}

// ---------------- init output with bias (head partials atomicAdd into it) ---
__global__ void k_outinit(float* __restrict__ out, const float* __restrict__ b) {
    int i = blockIdx.x * blockDim.x + threadIdx.x;
    if (i < NN) {
        out[i * 2 + 0] = b[0];
        out[i * 2 + 1] = b[1];
    }
}

// ---------------- aggregation: fp32 self + fp16 neighbor gather ----------------
// Lane owns 8 features: one uint4 (8 fp16) gather load per edge, fp32 accumulate.
template <int FD>
__global__ void agg_kernel(const float* __restrict__ h, const __half* __restrict__ h16,
                           __nv_bfloat16* __restrict__ zhi, __nv_bfloat16* __restrict__ zlo) {
    constexpr int TPN = FD / 8;          // threads per node (8 features each)
    constexpr int NPB = 256 / TPN;       // nodes per 256-thread block
    int local = threadIdx.x / TPN;
    int lane  = threadIdx.x % TPN;
    int node  = blockIdx.x * NPB + local;
    if (node >= NN) return;

    const float4* h4  = (const float4*)h;
    const uint4*  g16 = (const uint4*)h16;   // 8 halves per uint4
    int beg = g_rowptr[node];
    int end = g_rowptr[node + 1];

    float4 acc0 = h4[(size_t)node * (FD / 4) + lane * 2 + 0];   // self in fp32
    float4 acc1 = h4[(size_t)node * (FD / 4) + lane * 2 + 1];

    for (int e = beg; e < end; e++) {
        int s = g_esrc[e];
        uint4 p = __ldg(&g16[(size_t)s * TPN + lane]);
        float2 f0 = __half22float2(*(__half2*)&p.x);
        float2 f1 = __half22float2(*(__half2*)&p.y);
        float2 f2 = __half22float2(*(__half2*)&p.z);
        float2 f3 = __half22float2(*(__half2*)&p.w);
        acc0.x += f0.x; acc0.y += f0.y; acc0.z += f1.x; acc0.w += f1.y;
        acc1.x += f2.x; acc1.y += f2.y; acc1.z += f3.x; acc1.w += f3.y;
    }

    auto emit = [&](float4 a, int f4idx) {
        float vv[4] = {a.x, a.y, a.z, a.w};
        __nv_bfloat16 hh[4], ll[4];
#pragma unroll
        for (int q = 0; q < 4; q++) {
            hh[q] = __float2bfloat16_rn(vv[q]);
            ll[q] = __float2bfloat16_rn(vv[q] - __bfloat162float(hh[q]));
        }
        size_t off = (size_t)node * FD + f4idx * 4;
        *(uint2*)(zhi + off) = *(uint2*)hh;
        *(uint2*)(zlo + off) = *(uint2*)ll;
    };
    emit(acc0, lane * 2 + 0);
    emit(acc1, lane * 2 + 1);
}

// ---------------- mma.sync GEMM, 3-term bf16 split ----------------
// MODE 0: BN + ReLU -> bf16 hi/lo   MODE 1: bias + ReLU -> fp32 + fp16 copy
// MODE 3: bias, fused head: atomicAdd partials of row@outW into outO
static constexpr int STG_STRIDE = 32768;
static constexpr int A_LO = 8192, B_HI = 16384, B_LO = 24576;
static constexpr int SM_SCL = 65536, SM_SFT = 66560, SM_RED = 67584;
static constexpr int SMEM_BYTES = 68608;

template <int K, int MODE>
__global__ void __launch_bounds__(256, 1)
gemm_mma(const __nv_bfloat16* __restrict__ Ah, const __nv_bfloat16* __restrict__ Al,
         const __nv_bfloat16* __restrict__ Bh, const __nv_bfloat16* __restrict__ Bl,
         float* __restrict__ Cf, __half* __restrict__ C16,
         __nv_bfloat16* __restrict__ Chi, __nv_bfloat16* __restrict__ Clo,
         const float* __restrict__ bias,
         const float* __restrict__ gamma, const float* __restrict__ beta,
         const float* __restrict__ mu,    const float* __restrict__ var,
         const float* __restrict__ woW, float* __restrict__ outO) {
    extern __shared__ char sc[];
    uint32_t sb = smem_u32(sc);
    constexpr int NST = K / 32;

    int tid = threadIdx.x;
    int wid = tid >> 5;
    int lane = tid & 31;
    int wm = wid >> 2;
    int wn = wid & 3;
    int n0 = blockIdx.x * 128;
    int m0 = blockIdx.y * 128;

    if (tid < 256) {
        float s, t;
        if (MODE == 0) {
            float iv = rsqrtf(var[tid] + BN_EPS);
            s = gamma[tid] * iv;
            t = (bias[tid] - mu[tid]) * s + beta[tid];
        } else {
            s = 1.f;
            t = bias[tid];
        }
        ((float*)(sc + SM_SCL))[tid] = s;
        ((float*)(sc + SM_SFT))[tid] = t;
    }

    auto load_stage = [&](int s) {
        int buf = s & 1;
        uint32_t ss = sb + buf * STG_STRIDE;
        int k0 = s * 32;
#pragma unroll
        for (int r = 0; r < 2; r++) {
            int idx = tid + r * 256;
            int m = idx >> 2, c = idx & 3;
            uint32_t phys = m * 64 + ((c ^ ((m >> 1) & 3)) * 16);
            int gm = m0 + m;
            uint32_t sz = (gm < NN) ? 16u : 0u;
            size_t go = (size_t)(gm < NN ? gm : 0) * K + k0 + c * 8;
            cpasync16(ss + phys,        Ah + go, sz);
            cpasync16(ss + A_LO + phys, Al + go, sz);
        }
#pragma unroll
        for (int r = 0; r < 2; r++) {
            int idx = tid + r * 256;
            int kk = idx >> 4, j = idx & 15;
            uint32_t phys = kk * 256 + ((j ^ (kk & 7)) * 16);
            size_t go = (size_t)(k0 + kk) * 256 + n0 + j * 8;
            cpasync16(ss + B_HI + phys, Bh + go, 16);
            cpasync16(ss + B_LO + phys, Bl + go, 16);
        }
        asm volatile("cp.async.commit_group;" ::: "memory");
    };

    int ml = lane & 15, chalf = lane >> 4;
    uint32_t a_off[4];
    int a_sw[4];
#pragma unroll
    for (int t = 0; t < 4; t++) {
        int mrow = wm * 64 + t * 16 + ml;
        a_off[t] = mrow * 64;
        a_sw[t] = (mrow >> 1) & 3;
    }
    uint32_t b_off[4];
#pragma unroll
    for (int u = 0; u < 4; u++) {
        int j = wn * 4 + u;
        b_off[u] = (lane & 15) * 256 + ((j ^ (lane & 7)) * 16);
    }

    float acc[4][4][4];
#pragma unroll
    for (int t = 0; t < 4; t++)
#pragma unroll
        for (int u = 0; u < 4; u++)
#pragma unroll
            for (int r = 0; r < 4; r++) acc[t][u][r] = 0.f;

    load_stage(0);
    load_stage(1);

    for (int s = 0; s < NST; s++) {
        if (s + 1 < NST) asm volatile("cp.async.wait_group 1;" ::: "memory");
        else             asm volatile("cp.async.wait_group 0;" ::: "memory");
        __syncthreads();

        uint32_t ss = sb + (s & 1) * STG_STRIDE;
#pragma unroll
        for (int ks = 0; ks < 2; ks++) {
            uint32_t ah[4][4], al[4][4], bh[4][2], bl[4][2];
#pragma unroll
            for (int t = 0; t < 4; t++) {
                uint32_t co = (uint32_t)(((ks * 2 + chalf) ^ a_sw[t]) * 16);
                ldmx4(ah[t], ss + a_off[t] + co);
                ldmx4(al[t], ss + A_LO + a_off[t] + co);
            }
#pragma unroll
            for (int u = 0; u < 4; u++) {
                ldmx2t(bh[u], ss + B_HI + b_off[u] + ks * 4096);
                ldmx2t(bl[u], ss + B_LO + b_off[u] + ks * 4096);
            }
#pragma unroll
            for (int t = 0; t < 4; t++)
#pragma unroll
                for (int u = 0; u < 4; u++) {
                    mma16816(acc[t][u], ah[t], bh[u]);
                    mma16816(acc[t][u], ah[t], bl[u]);
                    mma16816(acc[t][u], al[t], bh[u]);
                }
        }
        __syncthreads();
        if (s + 2 < NST) load_stage(s + 2);
    }

    // -------- epilogue --------
    const float* scl = (const float*)(sc + SM_SCL);
    const float* sft = (const float*)(sc + SM_SFT);
    int g = lane >> 2, tg = lane & 3;

    if (MODE == 3) {
        float* red = (float*)(sc + SM_RED);
        red[tid] = 0.f;           // 256 floats = 128 rows x 2 outputs
        __syncthreads();
#pragma unroll
        for (int t = 0; t < 4; t++) {
#pragma unroll
            for (int half = 0; half < 2; half++) {
                int rl = wm * 64 + t * 16 + g + half * 8;
                float p0 = 0.f, p1 = 0.f;
#pragma unroll
                for (int u = 0; u < 4; u++) {
                    int col = n0 + wn * 32 + u * 8 + tg * 2;
                    float v0 = acc[t][u][half * 2 + 0] + sft[col];
                    float v1 = acc[t][u][half * 2 + 1] + sft[col + 1];
                    float w00 = __ldg(&woW[col * 2 + 0]),       w01 = __ldg(&woW[col * 2 + 1]);
                    float w10 = __ldg(&woW[(col + 1) * 2 + 0]), w11 = __ldg(&woW[(col + 1) * 2 + 1]);
                    p0 += v0 * w00 + v1 * w10;
                    p1 += v0 * w01 + v1 * w11;
                }
                atomicAdd(&red[rl * 2 + 0], p0);
                atomicAdd(&red[rl * 2 + 1], p1);
            }
        }
        __syncthreads();
        if (tid < 128) {
            int row = m0 + tid;
            if (row < NN) {
                atomicAdd(&outO[(size_t)row * 2 + 0], red[tid * 2 + 0]);
                atomicAdd(&outO[(size_t)row * 2 + 1], red[tid * 2 + 1]);
            }
        }
        return;
    }

#pragma unroll
    for (int t = 0; t < 4; t++) {
        int row0 = m0 + wm * 64 + t * 16 + g;
#pragma unroll
        for (int u = 0; u < 4; u++) {
            int col = n0 + wn * 32 + u * 8 + tg * 2;
            float s0 = scl[col], s1 = scl[col + 1];
            float f0 = sft[col], f1 = sft[col + 1];
#pragma unroll
            for (int half = 0; half < 2; half++) {
                int row = row0 + half * 8;
                if (row >= NN) continue;
                float v0 = acc[t][u][half * 2 + 0] * s0 + f0;
                float v1 = acc[t][u][half * 2 + 1] * s1 + f1;
                v0 = fmaxf(v0, 0.f); v1 = fmaxf(v1, 0.f);
                size_t o = (size_t)row * 256 + col;
                if (MODE == 0) {
                    float r0, r1;
                    uint32_t hp = pack_hi(v0, v1, r0, r1);
                    __nv_bfloat162 lp2 = __halves2bfloat162(
                        __float2bfloat16_rn(r0), __float2bfloat16_rn(r1));
                    *(uint32_t*)(Chi + o) = hp;
                    *(uint32_t*)(Clo + o) = *(uint32_t*)&lp2;
                } else {
                    *(float2*)(Cf + o) = make_float2(v0, v1);
                    __half2 h2 = __floats2half2_rn(v0, v1);
                    *(__half2*)(C16 + o) = h2;
                }
            }
        }
    }
}

// ---------------- launch: fully serial on the default stream ----------------
extern "C" void kernel_launch(void* const* d_in, const int* in_sizes, int n_in,
                              void* d_out, int out_size) {
    const float* x  = (const float*)d_in[0];
    const int*   ei = (const int*)d_in[1];
    const int* src = ei;
    const int* dst = ei + EE;

    const float* L[3][8];
    for (int l = 0; l < 3; l++)
        for (int p = 0; p < 8; p++)
            L[l][p] = (const float*)d_in[2 + l * 8 + p];
    const float* out_W = (const float*)d_in[26];
    const float* out_b = (const float*)d_in[27];

    __nv_bfloat16 *zhi, *zlo, *thi, *tlo, *wt;
    float *hA, *hB;
    __half *x16, *h16A, *h16B;
    cudaGetSymbolAddress((void**)&zhi, g_zhi);
    cudaGetSymbolAddress((void**)&zlo, g_zlo);
    cudaGetSymbolAddress((void**)&thi, g_thi);
    cudaGetSymbolAddress((void**)&tlo, g_tlo);
    cudaGetSymbolAddress((void**)&hA,  g_hA);
    cudaGetSymbolAddress((void**)&hB,  g_hB);
    cudaGetSymbolAddress((void**)&x16, g_x16);
    cudaGetSymbolAddress((void**)&h16A, g_h16A);
    cudaGetSymbolAddress((void**)&h16B, g_h16B);
    cudaGetSymbolAddress((void**)&wt,  g_w);
    auto WT = [&](int w, int hl) { return wt + ((size_t)w * 2 + hl) * HDIM * HDIM; };

    cudaFuncSetAttribute(gemm_mma<128, 0>, cudaFuncAttributeMaxDynamicSharedMemorySize, SMEM_BYTES);
    cudaFuncSetAttribute(gemm_mma<256, 0>, cudaFuncAttributeMaxDynamicSharedMemorySize, SMEM_BYTES);
    cudaFuncSetAttribute(gemm_mma<256, 1>, cudaFuncAttributeMaxDynamicSharedMemorySize, SMEM_BYTES);
    cudaFuncSetAttribute(gemm_mma<256, 3>, cudaFuncAttributeMaxDynamicSharedMemorySize, SMEM_BYTES);

    // ---- weight conversion + x fp16 copy + output init ----
    k_wconv<<<(128 * 256 + 255) / 256, 256>>>(L[0][0], 128, WT(0, 0), WT(0, 1));
    k_wconv<<<(256 * 256 + 255) / 256, 256>>>(L[0][6], 256, WT(1, 0), WT(1, 1));
    k_wconv<<<(256 * 256 + 255) / 256, 256>>>(L[1][0], 256, WT(2, 0), WT(2, 1));
    k_wconv<<<(256 * 256 + 255) / 256, 256>>>(L[1][6], 256, WT(3, 0), WT(3, 1));
    k_wconv<<<(256 * 256 + 255) / 256, 256>>>(L[2][0], 256, WT(4, 0), WT(4, 1));
    k_wconv<<<(256 * 256 + 255) / 256, 256>>>(L[2][6], 256, WT(5, 0), WT(5, 1));
    k_xconv<<<(NN * 128 + 255) / 256, 256>>>(x, x16);
    k_outinit<<<(NN + 255) / 256, 256>>>((float*)d_out, out_b);

    // ---- CSR build ----
    int nb_scan = (NN + 1023) / 1024;
    k_zero_counts<<<(NN + 255) / 256, 256>>>();
    k_hist<<<(EE + 255) / 256, 256>>>(dst);
    k_scan1<<<nb_scan, 1024>>>();
    k_scan2<<<1, 128>>>(nb_scan);
    k_scan3<<<nb_scan, 1024>>>();
    k_scatter<<<(EE + 255) / 256, 256>>>(src, dst);

    dim3 gg(2, (NN + 127) / 128);

    // ---- layer 1 (agg: self fp32 x, gather fp16 x16) ----
    agg_kernel<128><<<(NN + 15) / 16, 256>>>(x, x16, zhi, zlo);
    gemm_mma<128, 0><<<gg, 256, SMEM_BYTES>>>(zhi, zlo, WT(0, 0), WT(0, 1),
        nullptr, nullptr, thi, tlo, L[0][1], L[0][2], L[0][3], L[0][4], L[0][5], nullptr, nullptr);
    gemm_mma<256, 1><<<gg, 256, SMEM_BYTES>>>(thi, tlo, WT(1, 0), WT(1, 1),
        hA, h16A, nullptr, nullptr, L[0][7], nullptr, nullptr, nullptr, nullptr, nullptr, nullptr);

    // ---- layer 2 ----
    agg_kernel<256><<<(NN + 7) / 8, 256>>>(hA, h16A, zhi, zlo);
    gemm_mma<256, 0><<<gg, 256, SMEM_BYTES>>>(zhi, zlo, WT(2, 0), WT(2, 1),
        nullptr, nullptr, thi, tlo, L[1][1], L[1][2], L[1][3], L[1][4], L[1][5], nullptr, nullptr);
    gemm_mma<256, 1><<<gg, 256, SMEM_BYTES>>>(thi, tlo, WT(3, 0), WT(3, 1),
        hB, h16B, nullptr, nullptr, L[1][7], nullptr, nullptr, nullptr, nullptr, nullptr, nullptr);

    // ---- layer 3 + fused head ----
    agg_kernel<256><<<(NN + 7) / 8, 256>>>(hB, h16B, zhi, zlo);
    gemm_mma<256, 0><<<gg, 256, SMEM_BYTES>>>(zhi, zlo, WT(4, 0), WT(4, 1),
        nullptr, nullptr, thi, tlo, L[2][1], L[2][2], L[2][3], L[2][4], L[2][5], nullptr, nullptr);
    gemm_mma<256, 3><<<gg, 256, SMEM_BYTES>>>(thi, tlo, WT(5, 0), WT(5, 1),
        nullptr, nullptr, nullptr, nullptr, L[2][7], nullptr, nullptr, nullptr, nullptr,
        out_W, (float*)d_out);
}

// round 15
// speedup vs baseline: 2.0265x; 1.2384x over previous
#include <cuda_runtime.h>
#include <cuda_bf16.h>
#include <cuda_fp16.h>
#include <cstdint>
#include <math.h>

#define NN 100000
#define EE 3200000
#define HDIM 256
#define BN_EPS 1e-5f

// ---------------- device scratch ----------------
__device__ __half g_z16[(size_t)NN * HDIM];          // GEMM1 input (fp16)
__device__ __half g_t16[(size_t)NN * HDIM];          // GEMM2 input (fp16)
__device__ float  g_hA [(size_t)NN * HDIM];
__device__ float  g_hB [(size_t)NN * HDIM];
__device__ __half g_x16 [(size_t)NN * 128];          // fp16 gather copies
__device__ __half g_h16A[(size_t)NN * HDIM];
__device__ __half g_h16B[(size_t)NN * HDIM];
__device__ __half g_w  [6][2][HDIM * HDIM];          // W [K][256] fp16 hi/lo (k-major)
__device__ int g_counts[NN];
__device__ int g_rowptr[NN + 1];
__device__ int g_esrc[EE];
__device__ int g_bsums[128];

// ---------------- helpers ----------------
__device__ __forceinline__ uint32_t smem_u32(const void* p) {
    uint32_t a;
    asm("{ .reg .u64 t; cvta.to.shared.u64 t, %1; cvt.u32.u64 %0, t; }" : "=r"(a) : "l"(p));
    return a;
}
__device__ __forceinline__ void mma16816f(float* c, const uint32_t* a, const uint32_t* b) {
    asm volatile(
        "mma.sync.aligned.m16n8k16.row.col.f32.f16.f16.f32 "
        "{%0,%1,%2,%3}, {%4,%5,%6,%7}, {%8,%9}, {%0,%1,%2,%3};"
        : "+f"(c[0]), "+f"(c[1]), "+f"(c[2]), "+f"(c[3])
        : "r"(a[0]), "r"(a[1]), "r"(a[2]), "r"(a[3]), "r"(b[0]), "r"(b[1]));
}
__device__ __forceinline__ void ldmx4(uint32_t* r, uint32_t addr) {
    asm volatile("ldmatrix.sync.aligned.m8n8.x4.shared.b16 {%0,%1,%2,%3}, [%4];"
                 : "=r"(r[0]), "=r"(r[1]), "=r"(r[2]), "=r"(r[3]) : "r"(addr));
}
__device__ __forceinline__ void ldmx2t(uint32_t* r, uint32_t addr) {
    asm volatile("ldmatrix.sync.aligned.m8n8.x2.trans.shared.b16 {%0,%1}, [%2];"
                 : "=r"(r[0]), "=r"(r[1]) : "r"(addr));
}
__device__ __forceinline__ void cpasync16(uint32_t saddr, const void* gaddr, uint32_t sz) {
    asm volatile("cp.async.ca.shared.global [%0], [%1], 16, %2;"
                 :: "r"(saddr), "l"(gaddr), "r"(sz));
}

// ---------------- CSR build ----------------
__global__ void k_zero_counts() {
    int i = blockIdx.x * blockDim.x + threadIdx.x;
    if (i < NN) g_counts[i] = 0;
}
__global__ void k_hist(const int* __restrict__ dst) {
    int e = blockIdx.x * blockDim.x + threadIdx.x;
    if (e < EE) atomicAdd(&g_counts[dst[e]], 1);
}
__global__ void k_scan1() {
    __shared__ int sh[1024];
    int tid = threadIdx.x;
    int i = blockIdx.x * 1024 + tid;
    int v = (i < NN) ? g_counts[i] : 0;
    sh[tid] = v;
    __syncthreads();
    for (int off = 1; off < 1024; off <<= 1) {
        int t = (tid >= off) ? sh[tid - off] : 0;
        __syncthreads();
        sh[tid] += t;
        __syncthreads();
    }
    if (i < NN) g_rowptr[i + 1] = sh[tid];
    if (tid == 1023) g_bsums[blockIdx.x] = sh[tid];
}
__global__ void k_scan2(int nb) {
    __shared__ int sh[128];
    int tid = threadIdx.x;
    int v = (tid < nb) ? g_bsums[tid] : 0;
    sh[tid] = v;
    __syncthreads();
    for (int off = 1; off < 128; off <<= 1) {
        int t = (tid >= off) ? sh[tid - off] : 0;
        __syncthreads();
        sh[tid] += t;
        __syncthreads();
    }
    if (tid < nb) g_bsums[tid] = sh[tid] - v;
}
__global__ void k_scan3() {
    int i = blockIdx.x * 1024 + threadIdx.x;
    if (i < NN) {
        int inc = g_rowptr[i + 1] + g_bsums[blockIdx.x];
        g_rowptr[i + 1] = inc;
        g_counts[i] = inc - g_counts[i];   // exclusive prefix = rowptr[i]
    }
    if (i == 0) g_rowptr[0] = 0;
}
__global__ void k_scatter(const int* __restrict__ src, const int* __restrict__ dst) {
    int e = blockIdx.x * blockDim.x + threadIdx.x;
    if (e < EE) {
        int p = atomicAdd(&g_counts[dst[e]], 1);
        g_esrc[p] = src[e];
    }
}

// ---------------- weight convert: fp32 -> fp16 hi + fp16 lo ----------------
__global__ void k_wconv(const float* __restrict__ W, int K,
                        __half* __restrict__ hi, __half* __restrict__ lo) {
    int idx = blockIdx.x * blockDim.x + threadIdx.x;
    if (idx >= K * 256) return;
    float w = W[idx];
    __half h = __float2half_rn(w);
    hi[idx] = h;
    lo[idx] = __float2half_rn(w - __half2float(h));
}

// ---------------- x -> fp16 copy ----------------
__global__ void k_xconv(const float* __restrict__ x, __half* __restrict__ x16) {
    int i = blockIdx.x * blockDim.x + threadIdx.x;
    if (i < NN * 128) x16[i] = __float2half_rn(x[i]);
}

// ---------------- init output with bias ----------------
__global__ void k_outinit(float* __restrict__ out, const float* __restrict__ b) {
    int i = blockIdx.x * blockDim.x + threadIdx.x;
    if (i < NN) {
        out[i * 2 + 0] = b[0];
        out[i * 2 + 1] = b[1];
    }
}

// ---------------- aggregation: fp32 self + fp16 gather -> fp16 z ----------------
template <int FD>
__global__ void agg_kernel(const float* __restrict__ h, const __half* __restrict__ h16,
                           __half* __restrict__ z16) {
    constexpr int TPN = FD / 8;          // threads per node (8 features each)
    constexpr int NPB = 256 / TPN;
    int local = threadIdx.x / TPN;
    int lane  = threadIdx.x % TPN;
    int node  = blockIdx.x * NPB + local;
    if (node >= NN) return;

    const float4* h4  = (const float4*)h;
    const uint4*  g16 = (const uint4*)h16;
    int beg = g_rowptr[node];
    int end = g_rowptr[node + 1];

    float4 acc0 = h4[(size_t)node * (FD / 4) + lane * 2 + 0];
    float4 acc1 = h4[(size_t)node * (FD / 4) + lane * 2 + 1];

    for (int e = beg; e < end; e++) {
        int s = g_esrc[e];
        uint4 p = __ldg(&g16[(size_t)s * TPN + lane]);
        float2 f0 = __half22float2(*(__half2*)&p.x);
        float2 f1 = __half22float2(*(__half2*)&p.y);
        float2 f2 = __half22float2(*(__half2*)&p.z);
        float2 f3 = __half22float2(*(__half2*)&p.w);
        acc0.x += f0.x; acc0.y += f0.y; acc0.z += f1.x; acc0.w += f1.y;
        acc1.x += f2.x; acc1.y += f2.y; acc1.z += f3.x; acc1.w += f3.y;
    }

    uint4 outp;
    __half2 p0 = __floats2half2_rn(acc0.x, acc0.y);
    __half2 p1 = __floats2half2_rn(acc0.z, acc0.w);
    __half2 p2 = __floats2half2_rn(acc1.x, acc1.y);
    __half2 p3 = __floats2half2_rn(acc1.z, acc1.w);
    outp.x = *(uint32_t*)&p0; outp.y = *(uint32_t*)&p1;
    outp.z = *(uint32_t*)&p2; outp.w = *(uint32_t*)&p3;
    ((uint4*)z16)[(size_t)node * TPN + lane] = outp;
}

// ---------------- mma.sync GEMM, 2-term fp16 split (AhBh + AhBl) ----------------
// MODE 0: BN + ReLU -> fp16        MODE 1: bias + ReLU -> fp32 + fp16 copy
// MODE 3: bias, fused head -> atomicAdd into outO
static constexpr int STG_STRIDE = 24576;
static constexpr int B_HI = 8192, B_LO = 16384;
static constexpr int SM_SCL = 49152, SM_SFT = 50176, SM_RED = 51200;
static constexpr int SMEM_BYTES = 52224;

template <int K, int MODE>
__global__ void __launch_bounds__(256, 1)
gemm_mma(const __half* __restrict__ A,
         const __half* __restrict__ Bh, const __half* __restrict__ Bl,
         float* __restrict__ Cf, __half* __restrict__ C16,
         __half* __restrict__ Ct,
         const float* __restrict__ bias,
         const float* __restrict__ gamma, const float* __restrict__ beta,
         const float* __restrict__ mu,    const float* __restrict__ var,
         const float* __restrict__ woW, float* __restrict__ outO) {
    extern __shared__ char sc[];
    uint32_t sb = smem_u32(sc);
    constexpr int NST = K / 32;

    int tid = threadIdx.x;
    int wid = tid >> 5;
    int lane = tid & 31;
    int wm = wid >> 2;
    int wn = wid & 3;
    int n0 = blockIdx.x * 128;
    int m0 = blockIdx.y * 128;

    if (tid < 256) {
        float s, t;
        if (MODE == 0) {
            float iv = rsqrtf(var[tid] + BN_EPS);
            s = gamma[tid] * iv;
            t = (bias[tid] - mu[tid]) * s + beta[tid];
        } else {
            s = 1.f;
            t = bias[tid];
        }
        ((float*)(sc + SM_SCL))[tid] = s;
        ((float*)(sc + SM_SFT))[tid] = t;
    }

    auto load_stage = [&](int s) {
        int buf = s & 1;
        uint32_t ss = sb + buf * STG_STRIDE;
        int k0 = s * 32;
        // A: 128 rows x 64B (32 fp16), 512 chunks, 2 iters
#pragma unroll
        for (int r = 0; r < 2; r++) {
            int idx = tid + r * 256;
            int m = idx >> 2, c = idx & 3;
            uint32_t phys = m * 64 + ((c ^ ((m >> 1) & 3)) * 16);
            int gm = m0 + m;
            uint32_t sz = (gm < NN) ? 16u : 0u;
            size_t go = (size_t)(gm < NN ? gm : 0) * K + k0 + c * 8;
            cpasync16(ss + phys, A + go, sz);
        }
        // B hi/lo: 32 k-rows x 256B (128 fp16 of this n-half), 512 chunks each
#pragma unroll
        for (int r = 0; r < 2; r++) {
            int idx = tid + r * 256;
            int kk = idx >> 4, j = idx & 15;
            uint32_t phys = kk * 256 + ((j ^ (kk & 7)) * 16);
            size_t go = (size_t)(k0 + kk) * 256 + n0 + j * 8;
            cpasync16(ss + B_HI + phys, Bh + go, 16);
            cpasync16(ss + B_LO + phys, Bl + go, 16);
        }
        asm volatile("cp.async.commit_group;" ::: "memory");
    };

    int ml = lane & 15, chalf = lane >> 4;
    uint32_t a_off[4];
    int a_sw[4];
#pragma unroll
    for (int t = 0; t < 4; t++) {
        int mrow = wm * 64 + t * 16 + ml;
        a_off[t] = mrow * 64;
        a_sw[t] = (mrow >> 1) & 3;
    }
    uint32_t b_off[4];
#pragma unroll
    for (int u = 0; u < 4; u++) {
        int j = wn * 4 + u;
        b_off[u] = (lane & 15) * 256 + ((j ^ (lane & 7)) * 16);
    }

    float acc[4][4][4];
#pragma unroll
    for (int t = 0; t < 4; t++)
#pragma unroll
        for (int u = 0; u < 4; u++)
#pragma unroll
            for (int r = 0; r < 4; r++) acc[t][u][r] = 0.f;

    load_stage(0);
    load_stage(1);

    for (int s = 0; s < NST; s++) {
        if (s + 1 < NST) asm volatile("cp.async.wait_group 1;" ::: "memory");
        else             asm volatile("cp.async.wait_group 0;" ::: "memory");
        __syncthreads();

        uint32_t ss = sb + (s & 1) * STG_STRIDE;
#pragma unroll
        for (int ks = 0; ks < 2; ks++) {
            uint32_t ah[4][4], bh[4][2], bl[4][2];
#pragma unroll
            for (int t = 0; t < 4; t++) {
                uint32_t co = (uint32_t)(((ks * 2 + chalf) ^ a_sw[t]) * 16);
                ldmx4(ah[t], ss + a_off[t] + co);
            }
#pragma unroll
            for (int u = 0; u < 4; u++) {
                ldmx2t(bh[u], ss + B_HI + b_off[u] + ks * 4096);
                ldmx2t(bl[u], ss + B_LO + b_off[u] + ks * 4096);
            }
#pragma unroll
            for (int t = 0; t < 4; t++)
#pragma unroll
                for (int u = 0; u < 4; u++) {
                    mma16816f(acc[t][u], ah[t], bh[u]);
                    mma16816f(acc[t][u], ah[t], bl[u]);
                }
        }
        __syncthreads();
        if (s + 2 < NST) load_stage(s + 2);
    }

    // -------- epilogue --------
    const float* scl = (const float*)(sc + SM_SCL);
    const float* sft = (const float*)(sc + SM_SFT);
    int g = lane >> 2, tg = lane & 3;

    if (MODE == 3) {
        float* red = (float*)(sc + SM_RED);
        red[tid] = 0.f;
        __syncthreads();
#pragma unroll
        for (int t = 0; t < 4; t++) {
#pragma unroll
            for (int half = 0; half < 2; half++) {
                int rl = wm * 64 + t * 16 + g + half * 8;
                float p0 = 0.f, p1 = 0.f;
#pragma unroll
                for (int u = 0; u < 4; u++) {
                    int col = n0 + wn * 32 + u * 8 + tg * 2;
                    float v0 = acc[t][u][half * 2 + 0] + sft[col];
                    float v1 = acc[t][u][half * 2 + 1] + sft[col + 1];
                    float w00 = __ldg(&woW[col * 2 + 0]),       w01 = __ldg(&woW[col * 2 + 1]);
                    float w10 = __ldg(&woW[(col + 1) * 2 + 0]), w11 = __ldg(&woW[(col + 1) * 2 + 1]);
                    p0 += v0 * w00 + v1 * w10;
                    p1 += v0 * w01 + v1 * w11;
                }
                atomicAdd(&red[rl * 2 + 0], p0);
                atomicAdd(&red[rl * 2 + 1], p1);
            }
        }
        __syncthreads();
        if (tid < 128) {
            int row = m0 + tid;
            if (row < NN) {
                atomicAdd(&outO[(size_t)row * 2 + 0], red[tid * 2 + 0]);
                atomicAdd(&outO[(size_t)row * 2 + 1], red[tid * 2 + 1]);
            }
        }
        return;
    }

#pragma unroll
    for (int t = 0; t < 4; t++) {
        int row0 = m0 + wm * 64 + t * 16 + g;
#pragma unroll
        for (int u = 0; u < 4; u++) {
            int col = n0 + wn * 32 + u * 8 + tg * 2;
            float s0 = scl[col], s1 = scl[col + 1];
            float f0 = sft[col], f1 = sft[col + 1];
#pragma unroll
            for (int half = 0; half < 2; half++) {
                int row = row0 + half * 8;
                if (row >= NN) continue;
                float v0 = acc[t][u][half * 2 + 0] * s0 + f0;
                float v1 = acc[t][u][half * 2 + 1] * s1 + f1;
                v0 = fmaxf(v0, 0.f); v1 = fmaxf(v1, 0.f);
                size_t o = (size_t)row * 256 + col;
                if (MODE == 0) {
                    __half2 h2 = __floats2half2_rn(v0, v1);
                    *(__half2*)(Ct + o) = h2;
                } else {
                    *(float2*)(Cf + o) = make_float2(v0, v1);
                    __half2 h2 = __floats2half2_rn(v0, v1);
                    *(__half2*)(C16 + o) = h2;
                }
            }
        }
    }
}

// ---------------- launch: fully serial on the default stream ----------------
extern "C" void kernel_launch(void* const* d_in, const int* in_sizes, int n_in,
                              void* d_out, int out_size) {
    const float* x  = (const float*)d_in[0];
    const int*   ei = (const int*)d_in[1];
    const int* src = ei;
    const int* dst = ei + EE;

    const float* L[3][8];
    for (int l = 0; l < 3; l++)
        for (int p = 0; p < 8; p++)
            L[l][p] = (const float*)d_in[2 + l * 8 + p];
    const float* out_W = (const float*)d_in[26];
    const float* out_b = (const float*)d_in[27];

    __half *z16, *t16, *x16, *h16A, *h16B, *wt;
    float *hA, *hB;
    cudaGetSymbolAddress((void**)&z16, g_z16);
    cudaGetSymbolAddress((void**)&t16, g_t16);
    cudaGetSymbolAddress((void**)&hA,  g_hA);
    cudaGetSymbolAddress((void**)&hB,  g_hB);
    cudaGetSymbolAddress((void**)&x16, g_x16);
    cudaGetSymbolAddress((void**)&h16A, g_h16A);
    cudaGetSymbolAddress((void**)&h16B, g_h16B);
    cudaGetSymbolAddress((void**)&wt,  g_w);
    auto WT = [&](int w, int hl) { return wt + ((size_t)w * 2 + hl) * HDIM * HDIM; };

    cudaFuncSetAttribute(gemm_mma<128, 0>, cudaFuncAttributeMaxDynamicSharedMemorySize, SMEM_BYTES);
    cudaFuncSetAttribute(gemm_mma<256, 0>, cudaFuncAttributeMaxDynamicSharedMemorySize, SMEM_BYTES);
    cudaFuncSetAttribute(gemm_mma<256, 1>, cudaFuncAttributeMaxDynamicSharedMemorySize, SMEM_BYTES);
    cudaFuncSetAttribute(gemm_mma<256, 3>, cudaFuncAttributeMaxDynamicSharedMemorySize, SMEM_BYTES);

    // ---- weight conversion + x fp16 copy + output init ----
    k_wconv<<<(128 * 256 + 255) / 256, 256>>>(L[0][0], 128, WT(0, 0), WT(0, 1));
    k_wconv<<<(256 * 256 + 255) / 256, 256>>>(L[0][6], 256, WT(1, 0), WT(1, 1));
    k_wconv<<<(256 * 256 + 255) / 256, 256>>>(L[1][0], 256, WT(2, 0), WT(2, 1));
    k_wconv<<<(256 * 256 + 255) / 256, 256>>>(L[1][6], 256, WT(3, 0), WT(3, 1));
    k_wconv<<<(256 * 256 + 255) / 256, 256>>>(L[2][0], 256, WT(4, 0), WT(4, 1));
    k_wconv<<<(256 * 256 + 255) / 256, 256>>>(L[2][6], 256, WT(5, 0), WT(5, 1));
    k_xconv<<<(NN * 128 + 255) / 256, 256>>>(x, x16);
    k_outinit<<<(NN + 255) / 256, 256>>>((float*)d_out, out_b);

    // ---- CSR build ----
    int nb_scan = (NN + 1023) / 1024;
    k_zero_counts<<<(NN + 255) / 256, 256>>>();
    k_hist<<<(EE + 255) / 256, 256>>>(dst);
    k_scan1<<<nb_scan, 1024>>>();
    k_scan2<<<1, 128>>>(nb_scan);
    k_scan3<<<nb_scan, 1024>>>();
    k_scatter<<<(EE + 255) / 256, 256>>>(src, dst);

    dim3 gg(2, (NN + 127) / 128);

    // ---- layer 1 ----
    agg_kernel<128><<<(NN + 15) / 16, 256>>>(x, x16, z16);
    gemm_mma<128, 0><<<gg, 256, SMEM_BYTES>>>(z16, WT(0, 0), WT(0, 1),
        nullptr, nullptr, t16, L[0][1], L[0][2], L[0][3], L[0][4], L[0][5], nullptr, nullptr);
    gemm_mma<256, 1><<<gg, 256, SMEM_BYTES>>>(t16, WT(1, 0), WT(1, 1),
        hA, h16A, nullptr, L[0][7], nullptr, nullptr, nullptr, nullptr, nullptr, nullptr);

    // ---- layer 2 ----
    agg_kernel<256><<<(NN + 7) / 8, 256>>>(hA, h16A, z16);
    gemm_mma<256, 0><<<gg, 256, SMEM_BYTES>>>(z16, WT(2, 0), WT(2, 1),
        nullptr, nullptr, t16, L[1][1], L[1][2], L[1][3], L[1][4], L[1][5], nullptr, nullptr);
    gemm_mma<256, 1><<<gg, 256, SMEM_BYTES>>>(t16, WT(3, 0), WT(3, 1),
        hB, h16B, nullptr, L[1][7], nullptr, nullptr, nullptr, nullptr, nullptr, nullptr);

    // ---- layer 3 + fused head ----
    agg_kernel<256><<<(NN + 7) / 8, 256>>>(hB, h16B, z16);
    gemm_mma<256, 0><<<gg, 256, SMEM_BYTES>>>(z16, WT(4, 0), WT(4, 1),
        nullptr, nullptr, t16, L[2][1], L[2][2], L[2][3], L[2][4], L[2][5], nullptr, nullptr);
    gemm_mma<256, 3><<<gg, 256, SMEM_BYTES>>>(t16, WT(5, 0), WT(5, 1),
        nullptr, nullptr, nullptr, L[2][7], nullptr, nullptr, nullptr, nullptr,
        out_W, (float*)d_out);
}